// round 8
// baseline (speedup 1.0000x reference)
#include <cuda_runtime.h>

#define BB 4
#define NN 2048
#define EE (NN*(NN-1)/2)        // 2,096,128
#define NPAIR (NN/2)            // 1024
#define PAIRS 4                 // pairs per block
#define GX (NPAIR/PAIRS)        // 256
#define NBLKS (GX*BB)           // 1024
#define TPB 256
#define NWARP (TPB/32)

__device__ float g_partial[NBLKS];
__device__ unsigned int g_count = 0;

struct Consts {
    float f, omf;
    float qt00, qt01, qt10, qt11;   // qt[a][x] = lik(x)*pr(a)/ev(a==x)
};

__device__ __forceinline__ float edge_term(int a, float uu, float xv, const Consts& c)
{
    const float p1 = a ? c.omf : c.f;            // P(x_t = 1)
    const bool  x  = uu < p1;
    const float q0 = x ? c.qt01 : c.qt00;        // a = 0
    const float q1 = x ? c.qt11 : c.qt10;        // a = 1
    const float qt = a ? q1 : q0;
    // softplus(-|x|) = log1p(exp(-|x|)) via EX2 + LG2
    const float sp = 0.69314718056f * __log2f(1.0f + __expf(-fabsf(xv)));
    return fmaxf(xv, 0.0f) - xv * qt + sp;
}

// Process one row pair (i1 short, i2 long). ALL loads for both rows are issued
// into registers before any compute, so a thread holds up to 24 LDGs in flight.
// __launch_bounds__(256,3) gives an 84-reg budget so ptxas keeps the batch live.
__device__ __forceinline__ void pair_sum(const int*   __restrict__ a1p,
                                         const float* __restrict__ u1p,
                                         const float* __restrict__ q1p, int i1,
                                         const int*   __restrict__ a2p,
                                         const float* __restrict__ u2p,
                                         const float* __restrict__ q2p, int i2,
                                         int tid, const Consts& c,
                                         float& s0, float& s1, float& s2, float& s3)
{
    const int g = tid * 8;
    const bool full2 = (g + 8 <= i2);
    const bool full1 = (g + 8 <= i1);

    int4   a20, a21, a10, a11;
    float4 u20, u21, u10, u11;
    float  q2v[8], q1v[8];

    // ---- load phase (no compute in between) ----
    if (full2) {
        a20 = *reinterpret_cast<const int4*>(a2p + g);
        a21 = *reinterpret_cast<const int4*>(a2p + g + 4);
        u20 = *reinterpret_cast<const float4*>(u2p + g);
        u21 = *reinterpret_cast<const float4*>(u2p + g + 4);
        #pragma unroll
        for (int k = 0; k < 8; k++) q2v[k] = q2p[g + k];
    }
    if (full1) {
        a10 = *reinterpret_cast<const int4*>(a1p + g);
        a11 = *reinterpret_cast<const int4*>(a1p + g + 4);
        u10 = *reinterpret_cast<const float4*>(u1p + g);
        u11 = *reinterpret_cast<const float4*>(u1p + g + 4);
        #pragma unroll
        for (int k = 0; k < 8; k++) q1v[k] = q1p[g + k];
    }

    // ---- compute phase ----
    if (full2) {
        s0 += edge_term(a20.x, u20.x, q2v[0], c);
        s1 += edge_term(a20.y, u20.y, q2v[1], c);
        s2 += edge_term(a20.z, u20.z, q2v[2], c);
        s3 += edge_term(a20.w, u20.w, q2v[3], c);
        s0 += edge_term(a21.x, u21.x, q2v[4], c);
        s1 += edge_term(a21.y, u21.y, q2v[5], c);
        s2 += edge_term(a21.z, u21.z, q2v[6], c);
        s3 += edge_term(a21.w, u21.w, q2v[7], c);
    }
    if (full1) {
        s0 += edge_term(a10.x, u10.x, q1v[0], c);
        s1 += edge_term(a10.y, u10.y, q1v[1], c);
        s2 += edge_term(a10.z, u10.z, q1v[2], c);
        s3 += edge_term(a10.w, u10.w, q1v[3], c);
        s0 += edge_term(a11.x, u11.x, q1v[4], c);
        s1 += edge_term(a11.y, u11.y, q1v[5], c);
        s2 += edge_term(a11.z, u11.z, q1v[6], c);
        s3 += edge_term(a11.w, u11.w, q1v[7], c);
    }

    // ---- tails (at most one group per row) ----
    if (!full2 && g < i2) {
        float s = 0.0f;
        for (int j = g; j < i2; j++) s += edge_term(a2p[j], u2p[j], q2p[j], c);
        s0 += s;
    }
    if (!full1 && g < i1) {
        float s = 0.0f;
        for (int j = g; j < i1; j++) s += edge_term(a1p[j], u1p[j], q1p[j], c);
        s1 += s;
    }
}

__global__ __launch_bounds__(TPB, 3) void diffusion_fused_kernel(
    const int*   __restrict__ adj,   // [B, N, N] int32
    const int*   __restrict__ t,     // [B]
    const float* __restrict__ u,     // [B, N, N]
    const float* __restrict__ q,     // [B, E]
    float* __restrict__ out)
{
    const int b   = blockIdx.y;
    const int tid = threadIdx.x;

    // Per-batch flip probabilities: f = 0.5*(1 - 0.98^(t+1)); t-1 wraps to 999.
    const int tb = t[b];
    const double L2_098 = -0.0291463456595169;   // log2(0.98)
    const float pw  = exp2f((float)((double)(tb + 1) * L2_098));
    const int   tp  = (tb == 0) ? 999 : (tb - 1);
    const float pwp = exp2f((float)((double)(tp + 1) * L2_098));

    Consts c;
    c.f   = 0.5f * (1.0f - pw);
    c.omf = 1.0f - c.f;
    const float fp   = 0.5f * (1.0f - pwp);
    const float omfp = 1.0f - fp;
    const float rf   = __fdividef(1.0f, c.f);
    const float romf = __fdividef(1.0f, c.omf);
    // qt[a][x] = lik(x) * pr(a) / ev(a==x);  ev: equal -> omf, diff -> f
    c.qt00 = 0.01f * fp   * romf;
    c.qt01 = 0.99f * fp   * rf;
    c.qt10 = 0.01f * omfp * rf;
    c.qt11 = 0.99f * omfp * romf;

    const size_t bnn = (size_t)b * NN * NN;
    const size_t bee = (size_t)b * EE;
    const int*   adjb = adj + bnn;
    const float* ub   = u + bnn;
    const float* qb   = q + bee;

    float s0 = 0.0f, s1 = 0.0f, s2 = 0.0f, s3 = 0.0f;

    #pragma unroll 1
    for (int m = 0; m < PAIRS; m++) {
        const int p  = blockIdx.x * PAIRS + m;
        const int i1 = p;              // short row
        const int i2 = NN - 1 - p;     // long row (i1 + i2 = 2047)
        pair_sum(adjb + (size_t)i1 * NN, ub + (size_t)i1 * NN,
                 qb + ((size_t)i1 * (size_t)(i1 - 1)) / 2, i1,
                 adjb + (size_t)i2 * NN, ub + (size_t)i2 * NN,
                 qb + ((size_t)i2 * (size_t)(i2 - 1)) / 2, i2,
                 tid, c, s0, s1, s2, s3);
    }

    float s = (s0 + s1) + (s2 + s3);
    #pragma unroll
    for (int o = 16; o > 0; o >>= 1)
        s += __shfl_xor_sync(0xFFFFFFFFu, s, o);

    __shared__ float wsum[NWARP];
    __shared__ bool  isLast;
    const int wid = tid >> 5, lid = tid & 31;
    if (lid == 0) wsum[wid] = s;
    __syncthreads();

    if (tid == 0) {
        float bs = 0.0f;
        #pragma unroll
        for (int w = 0; w < NWARP; w++) bs += wsum[w];
        g_partial[blockIdx.y * gridDim.x + blockIdx.x] = bs;
        __threadfence();
        unsigned int old = atomicAdd(&g_count, 1u);
        isLast = (old == (unsigned)(NBLKS - 1));
    }
    __syncthreads();

    if (isLast) {
        __shared__ double dsum[TPB];
        double ds = 0.0;
        for (int idx = tid; idx < NBLKS; idx += TPB)
            ds += (double)g_partial[idx];
        dsum[tid] = ds;
        __syncthreads();
        #pragma unroll
        for (int o = TPB / 2; o > 0; o >>= 1) {
            if (tid < o) dsum[tid] += dsum[tid + o];
            __syncthreads();
        }
        if (tid == 0) {
            out[0] = (float)(dsum[0] / ((double)BB * (double)EE));
            g_count = 0;   // reset for next graph replay
        }
    }
}

extern "C" void kernel_launch(void* const* d_in, const int* in_sizes, int n_in,
                              void* d_out, int out_size)
{
    const int*   adj = (const int*)  d_in[0];
    const int*   t   = (const int*)  d_in[1];
    const float* u   = (const float*)d_in[2];
    const float* q   = (const float*)d_in[3];
    float* out = (float*)d_out;

    dim3 grid(GX, BB);
    diffusion_fused_kernel<<<grid, TPB>>>(adj, t, u, q, out);
}

// round 9
// speedup vs baseline: 1.2086x; 1.2086x over previous
#include <cuda_runtime.h>

#define BB 4
#define NN 2048
#define EE (NN*(NN-1)/2)        // 2,096,128
#define NPAIR (NN/2)            // 1024
#define PAIRS 4                 // pairs per block
#define GX (NPAIR/PAIRS)        // 256
#define NBLKS (GX*BB)           // 1024
#define TPB 256
#define NWARP (TPB/32)

__device__ float g_partial[NBLKS];
__device__ unsigned int g_count = 0;

struct Consts {
    float f, omf;
    float qt00, qt01, qt10, qt11;   // qt[a][x] = lik(x)*pr(a)/ev(a==x)
};

__device__ __forceinline__ void pf_l2(const void* p)
{
    asm volatile("prefetch.global.L2 [%0];" :: "l"(p));
}

__device__ __forceinline__ float edge_term(int a, float uu, float xv, const Consts& c)
{
    const float p1 = a ? c.omf : c.f;            // P(x_t = 1)
    const bool  x  = uu < p1;
    const float q0 = x ? c.qt01 : c.qt00;        // a = 0
    const float q1 = x ? c.qt11 : c.qt10;        // a = 1
    const float qt = a ? q1 : q0;
    // softplus(-|x|) = log1p(exp(-|x|)) via EX2 + LG2
    const float sp = 0.69314718056f * __log2f(1.0f + __expf(-fabsf(xv)));
    return fmaxf(xv, 0.0f) - xv * qt + sp;
}

// R7 mapping (best measured): thread tid owns elements [8*tid, 8*tid+8).
// 12 loads issued straight-line, consumed into 4 independent accumulators.
__device__ __forceinline__ void row_sum(const int*   __restrict__ arow,
                                        const float* __restrict__ urow,
                                        const float* __restrict__ qrow,
                                        int len, int tid, const Consts& c,
                                        float& s0, float& s1, float& s2, float& s3)
{
    const int g = tid * 8;
    if (g + 8 <= len) {
        const int4   a0 = *reinterpret_cast<const int4*>(arow + g);
        const int4   a1 = *reinterpret_cast<const int4*>(arow + g + 4);
        const float4 u0 = *reinterpret_cast<const float4*>(urow + g);
        const float4 u1 = *reinterpret_cast<const float4*>(urow + g + 4);
        const float  x0 = qrow[g + 0], x1 = qrow[g + 1], x2 = qrow[g + 2], x3 = qrow[g + 3];
        const float  x4 = qrow[g + 4], x5 = qrow[g + 5], x6 = qrow[g + 6], x7 = qrow[g + 7];
        s0 += edge_term(a0.x, u0.x, x0, c);
        s1 += edge_term(a0.y, u0.y, x1, c);
        s2 += edge_term(a0.z, u0.z, x2, c);
        s3 += edge_term(a0.w, u0.w, x3, c);
        s0 += edge_term(a1.x, u1.x, x4, c);
        s1 += edge_term(a1.y, u1.y, x5, c);
        s2 += edge_term(a1.z, u1.z, x6, c);
        s3 += edge_term(a1.w, u1.w, x7, c);
    } else if (g < len) {
        float s = 0.0f;
        for (int j = g; j < len; j++)
            s += edge_term(arow[j], urow[j], qrow[j], c);
        s0 += s;
    }
}

__global__ __launch_bounds__(TPB) void diffusion_fused_kernel(
    const int*   __restrict__ adj,   // [B, N, N] int32
    const int*   __restrict__ t,     // [B]
    const float* __restrict__ u,     // [B, N, N]
    const float* __restrict__ q,     // [B, E]
    float* __restrict__ out)
{
    const int b   = blockIdx.y;
    const int tid = threadIdx.x;

    // Per-batch flip probabilities: f = 0.5*(1 - 0.98^(t+1)); t-1 wraps to 999.
    const int tb = t[b];
    const double L2_098 = -0.0291463456595169;   // log2(0.98)
    const float pw  = exp2f((float)((double)(tb + 1) * L2_098));
    const int   tp  = (tb == 0) ? 999 : (tb - 1);
    const float pwp = exp2f((float)((double)(tp + 1) * L2_098));

    Consts c;
    c.f   = 0.5f * (1.0f - pw);
    c.omf = 1.0f - c.f;
    const float fp   = 0.5f * (1.0f - pwp);
    const float omfp = 1.0f - fp;
    const float rf   = __fdividef(1.0f, c.f);
    const float romf = __fdividef(1.0f, c.omf);
    // qt[a][x] = lik(x) * pr(a) / ev(a==x);  ev: equal -> omf, diff -> f
    c.qt00 = 0.01f * fp   * romf;
    c.qt01 = 0.99f * fp   * rf;
    c.qt10 = 0.01f * omfp * rf;
    c.qt11 = 0.99f * omfp * romf;

    const size_t bnn = (size_t)b * NN * NN;
    const size_t bee = (size_t)b * EE;
    const int*   adjb = adj + bnn;
    const float* ub   = u + bnn;
    const float* qb   = q + bee;

    float s0 = 0.0f, s1 = 0.0f, s2 = 0.0f, s3 = 0.0f;
    const int g = tid * 8;

    #pragma unroll 1
    for (int m = 0; m < PAIRS; m++) {
        const int p  = blockIdx.x * PAIRS + m;
        const int i1 = p;              // short row
        const int i2 = NN - 1 - p;     // long row (i1 + i2 = 2047)

        // Prefetch next pair's data into L2 (no regs, no scoreboard) so the
        // demand LDGs of iteration m+1 hit L2 instead of DRAM.
        if (m + 1 < PAIRS) {
            const int pn = p + 1;
            const int n1 = pn, n2 = NN - 1 - pn;
            const size_t r2 = (size_t)n2 * NN;
            const size_t r1 = (size_t)n1 * NN;
            const size_t e2 = ((size_t)n2 * (size_t)(n2 - 1)) / 2;
            const size_t e1 = ((size_t)n1 * (size_t)(n1 - 1)) / 2;
            if (g < n2) {
                pf_l2(adjb + r2 + g);
                pf_l2(ub + r2 + g);
                pf_l2(qb + e2 + g);
            }
            if (g < n1) {
                pf_l2(adjb + r1 + g);
                pf_l2(ub + r1 + g);
                pf_l2(qb + e1 + g);
            }
        }

        row_sum(adjb + (size_t)i1 * NN, ub + (size_t)i1 * NN,
                qb + ((size_t)i1 * (size_t)(i1 - 1)) / 2, i1, tid, c, s0, s1, s2, s3);
        row_sum(adjb + (size_t)i2 * NN, ub + (size_t)i2 * NN,
                qb + ((size_t)i2 * (size_t)(i2 - 1)) / 2, i2, tid, c, s0, s1, s2, s3);
    }

    float s = (s0 + s1) + (s2 + s3);
    #pragma unroll
    for (int o = 16; o > 0; o >>= 1)
        s += __shfl_xor_sync(0xFFFFFFFFu, s, o);

    __shared__ float wsum[NWARP];
    __shared__ bool  isLast;
    const int wid = tid >> 5, lid = tid & 31;
    if (lid == 0) wsum[wid] = s;
    __syncthreads();

    if (tid == 0) {
        float bs = 0.0f;
        #pragma unroll
        for (int w = 0; w < NWARP; w++) bs += wsum[w];
        g_partial[blockIdx.y * gridDim.x + blockIdx.x] = bs;
        __threadfence();
        unsigned int old = atomicAdd(&g_count, 1u);
        isLast = (old == (unsigned)(NBLKS - 1));
    }
    __syncthreads();

    if (isLast) {
        __shared__ double dsum[TPB];
        double ds = 0.0;
        for (int idx = tid; idx < NBLKS; idx += TPB)
            ds += (double)g_partial[idx];
        dsum[tid] = ds;
        __syncthreads();
        #pragma unroll
        for (int o = TPB / 2; o > 0; o >>= 1) {
            if (tid < o) dsum[tid] += dsum[tid + o];
            __syncthreads();
        }
        if (tid == 0) {
            out[0] = (float)(dsum[0] / ((double)BB * (double)EE));
            g_count = 0;   // reset for next graph replay
        }
    }
}

extern "C" void kernel_launch(void* const* d_in, const int* in_sizes, int n_in,
                              void* d_out, int out_size)
{
    const int*   adj = (const int*)  d_in[0];
    const int*   t   = (const int*)  d_in[1];
    const float* u   = (const float*)d_in[2];
    const float* q   = (const float*)d_in[3];
    float* out = (float*)d_out;

    dim3 grid(GX, BB);
    diffusion_fused_kernel<<<grid, TPB>>>(adj, t, u, q, out);
}